// round 8
// baseline (speedup 1.0000x reference)
#include <cuda_runtime.h>
#include <cuda_bf16.h>

#define NJ   24
#define FEAT 6
#define HID  7

// Identity order is topological: PARENTS[j] < j for all j>0.
static __device__ __forceinline__ constexpr int PARENT(int j) {
    constexpr int P[NJ] = {-1,0,0,0,1,2,3,4,5,6,7,8,9,9,9,12,13,14,16,17,18,19,20,21};
    return P[j];
}

__device__ __forceinline__ float comp(const float4& v, int c) {
    return c == 0 ? v.x : (c == 1 ? v.y : (c == 2 ? v.z : v.w));
}

// Constant-memory weights, rows padded to 8 floats (2x float4 per row).
//  cW1[j*14 + r*2 + {0,1}] : W1[j][r][0..6] (+1 pad)
//  cB1[j*2 + {0,1}]        : b1[j][0..6]   (+1 pad)
//  cW2[j*12 + q*2 + {0,1}] : W2[j][q][0..6](+1 pad)
//  cB2[j*2 + {0,1}]        : b2[j][0..5]   (+2 pad)
__constant__ float4 cW1[NJ * 14];   // 1344 floats
__constant__ float4 cB1[NJ * 2];    //  192
__constant__ float4 cW2[NJ * 12];   // 1152
__constant__ float4 cB2[NJ * 2];    //  192

__global__ __launch_bounds__(256, 2)
void se1d_kernel(const float* __restrict__ x,
                 float* __restrict__ out, int B, int Qh)
{
    const int g = blockIdx.x * 256 + threadIdx.x;
    if (g >= Qh) return;

    // Two sample streams, each internally coalesced across the warp.
    const long s0 = g;
    const long s1 = (long)g + Qh;
    const bool a1 = s1 < B;
    const long r1 = a1 ? s1 : (long)(B - 1);

    const float4* xv0 = (const float4*)(x + s0 * NJ);
    const float4* xv1 = (const float4*)(x + r1 * NJ);
    float* o0 = out + s0 * (NJ * FEAT);
    float* o1 = out + s1 * (NJ * FEAT);

    // Compile-time indexed only -> registers; liveness prunes dead joints.
    float f0[NJ][FEAT], f1[NJ][FEAT];
    float4 xc0, xc1;

    #pragma unroll
    for (int j = 0; j < NJ; j++) {
        if ((j & 3) == 0) {
            xc0 = __ldcs(xv0 + (j >> 2));
            xc1 = __ldcs(xv1 + (j >> 2));
        }
        const int cc = j & 3;

        float in0[HID], in1[HID];
        in0[0] = comp(xc0, cc);
        in1[0] = comp(xc1, cc);
        if (j == 0) {
            #pragma unroll
            for (int f = 0; f < FEAT; f++) { in0[1 + f] = 0.f; in1[1 + f] = 0.f; }
        } else {
            const int p = PARENT(j);
            #pragma unroll
            for (int f = 0; f < FEAT; f++) { in0[1 + f] = f0[p][f]; in1[1 + f] = f1[p][f]; }
        }

        // ---- Layer 1: h = relu(W1 @ inp + b1). Weights via constant port
        //      (warp-uniform broadcast, no L1tex wavefronts).
        float4 bb0 = cB1[j * 2 + 0];
        float4 bb1 = cB1[j * 2 + 1];
        const float bv[8] = {bb0.x, bb0.y, bb0.z, bb0.w, bb1.x, bb1.y, bb1.z, bb1.w};
        float h0[HID], h1[HID];
        #pragma unroll
        for (int r = 0; r < HID; r++) {
            float4 w0 = cW1[j * 14 + r * 2 + 0];
            float4 w1 = cW1[j * 14 + r * 2 + 1];
            float a0 = bv[r], a1v = bv[r];
            a0 = fmaf(w0.x, in0[0], a0);  a1v = fmaf(w0.x, in1[0], a1v);
            a0 = fmaf(w0.y, in0[1], a0);  a1v = fmaf(w0.y, in1[1], a1v);
            a0 = fmaf(w0.z, in0[2], a0);  a1v = fmaf(w0.z, in1[2], a1v);
            a0 = fmaf(w0.w, in0[3], a0);  a1v = fmaf(w0.w, in1[3], a1v);
            a0 = fmaf(w1.x, in0[4], a0);  a1v = fmaf(w1.x, in1[4], a1v);
            a0 = fmaf(w1.y, in0[5], a0);  a1v = fmaf(w1.y, in1[5], a1v);
            a0 = fmaf(w1.z, in0[6], a0);  a1v = fmaf(w1.z, in1[6], a1v);
            h0[r] = fmaxf(a0, 0.f);
            h1[r] = fmaxf(a1v, 0.f);
        }

        // ---- Layer 2: f = relu(W2 @ h + b2)
        float4 cb0 = cB2[j * 2 + 0];
        float4 cb1 = cB2[j * 2 + 1];
        const float cv[8] = {cb0.x, cb0.y, cb0.z, cb0.w, cb1.x, cb1.y, cb1.z, cb1.w};
        #pragma unroll
        for (int q = 0; q < FEAT; q++) {
            float4 w0 = cW2[j * 12 + q * 2 + 0];
            float4 w1 = cW2[j * 12 + q * 2 + 1];
            float a0 = cv[q], a1v = cv[q];
            a0 = fmaf(w0.x, h0[0], a0);  a1v = fmaf(w0.x, h1[0], a1v);
            a0 = fmaf(w0.y, h0[1], a0);  a1v = fmaf(w0.y, h1[1], a1v);
            a0 = fmaf(w0.z, h0[2], a0);  a1v = fmaf(w0.z, h1[2], a1v);
            a0 = fmaf(w0.w, h0[3], a0);  a1v = fmaf(w0.w, h1[3], a1v);
            a0 = fmaf(w1.x, h0[4], a0);  a1v = fmaf(w1.x, h1[4], a1v);
            a0 = fmaf(w1.y, h0[5], a0);  a1v = fmaf(w1.y, h1[5], a1v);
            a0 = fmaf(w1.z, h0[6], a0);  a1v = fmaf(w1.z, h1[6], a1v);
            f0[j][q] = fmaxf(a0, 0.f);
            f1[j][q] = fmaxf(a1v, 0.f);
        }

        // ---- Paired-joint streaming stores: joints (j-1, j) -> 3x STG.128 per sample.
        if (j & 1) {
            float4 v0 = make_float4(f0[j-1][0], f0[j-1][1], f0[j-1][2], f0[j-1][3]);
            float4 v1 = make_float4(f0[j-1][4], f0[j-1][5], f0[j][0],   f0[j][1]);
            float4 v2 = make_float4(f0[j][2],   f0[j][3],   f0[j][4],   f0[j][5]);
            float4* p0 = (float4*)(o0 + (j - 1) * FEAT);
            __stcs(p0 + 0, v0); __stcs(p0 + 1, v1); __stcs(p0 + 2, v2);
            if (a1) {
                float4 u0 = make_float4(f1[j-1][0], f1[j-1][1], f1[j-1][2], f1[j-1][3]);
                float4 u1 = make_float4(f1[j-1][4], f1[j-1][5], f1[j][0],   f1[j][1]);
                float4 u2 = make_float4(f1[j][2],   f1[j][3],   f1[j][4],   f1[j][5]);
                float4* p1 = (float4*)(o1 + (j - 1) * FEAT);
                __stcs(p1 + 0, u0); __stcs(p1 + 1, u1); __stcs(p1 + 2, u2);
            }
        }
    }
}

extern "C" void kernel_launch(void* const* d_in, const int* in_sizes, int n_in,
                              void* d_out, int out_size)
{
    const float* x  = (const float*)d_in[0];
    const float* W1 = (const float*)d_in[1];
    const float* b1 = (const float*)d_in[2];
    const float* W2 = (const float*)d_in[3];
    const float* b2 = (const float*)d_in[4];
    float* out = (float*)d_out;

    // Strided D2D copies: pad 7-float rows to 8-float (32B) constant rows.
    // Graph-capturable (async memcpy nodes), no allocation.
    void *pW1, *pB1, *pW2, *pB2;
    cudaGetSymbolAddress(&pW1, cW1);
    cudaGetSymbolAddress(&pB1, cB1);
    cudaGetSymbolAddress(&pW2, cW2);
    cudaGetSymbolAddress(&pB2, cB2);

    cudaMemcpy2DAsync(pW1, 32, W1, 28, 28, NJ * HID,
                      cudaMemcpyDeviceToDevice, 0);          // 168 rows of 7 floats
    cudaMemcpy2DAsync(pB1, 32, b1, 28, 28, NJ,
                      cudaMemcpyDeviceToDevice, 0);          // 24 rows of 7 floats
    cudaMemcpy2DAsync(pW2, 32, W2, 28, 28, NJ * FEAT,
                      cudaMemcpyDeviceToDevice, 0);          // 144 rows of 7 floats
    cudaMemcpy2DAsync(pB2, 32, b2, 24, 24, NJ,
                      cudaMemcpyDeviceToDevice, 0);          // 24 rows of 6 floats

    const int B  = in_sizes[0] / NJ;
    const int Qh = (B + 1) / 2;
    const int grid = (Qh + 255) / 256;
    se1d_kernel<<<grid, 256>>>(x, out, B, Qh);
}